// round 12
// baseline (speedup 1.0000x reference)
#include <cuda_runtime.h>
#include <cuda_bf16.h>
#include <math.h>

#define BB   2
#define TT   1024
#define CC   2048
#define NH   16
#define HS   128
#define NLQ  512
#define NLKV 512
#define DHR  64
#define KCAT 576

// ---------------- scratch ----------------
__device__ float g_keff[16l * 512 * 512];       // keff_t[h][k][q] (q contiguous, tf32)
__device__ float g_veff[2048l * 512];           // veff_t[j][k]   (k contiguous, tf32)
__device__ float g_cq  [2048l * 512];
__device__ float g_ckr [2048l * 64];
__device__ float g_cqr [2048l * 1024];
__device__ float g_kcat[2048l * 576];
__device__ float g_qcat[32l * 1024 * 576];
__device__ float g_attn[32l * 1024 * 1024];
__device__ float g_lat [32l * 1024 * 512];
__device__ float g_wbuf[14286848];              // tf32-rounded copies of inputs

// offsets into g_wbuf (floats)
#define OFF_X     0l
#define OFF_WDQ   4194304l
#define OFF_WDKV  5242880l
#define OFF_WUK   6291456l
#define OFF_WUQ   7340032l
#define OFF_WUV   8388608l
#define OFF_WQR   9437184l
#define OFF_WKR   9961472l
#define OFF_WO    10092544l

struct GP {
    const float* A; const float* B; float* C;
    int M, N, K;
    long sAm, sAk, sBk, sBn, ldc;
    int aDiv, aMod, bDiv, bMod, cDiv, cMod;
    long aS1, aS2, bS1, bS2, cS1, cS2;
    int kSplit;
    int mode;    // 0 plain, 1 causal tile-skip, 2 causal k-stop
    int roundC;  // 1 -> round output to tf32 on store (non-splitK path)
};

__device__ __forceinline__ unsigned f2tf32(float x) {
    unsigned u;
    asm("cvt.rna.tf32.f32 %0, %1;" : "=r"(u) : "f"(x));
    return u;
}

__device__ __forceinline__ void mma_tf32(float* d, const unsigned* a,
                                         const unsigned* b) {
    asm volatile(
        "mma.sync.aligned.m16n8k8.row.col.f32.tf32.tf32.f32 "
        "{%0,%1,%2,%3}, {%4,%5,%6,%7}, {%8,%9}, {%0,%1,%2,%3};\n"
        : "+f"(d[0]), "+f"(d[1]), "+f"(d[2]), "+f"(d[3])
        : "r"(a[0]), "r"(a[1]), "r"(a[2]), "r"(a[3]),
          "r"(b[0]), "r"(b[1]));
}

#define CP16(dst, src) \
    asm volatile("cp.async.cg.shared.global [%0], [%1], 16;" \
                 :: "r"(dst), "l"(src))
#define CP_COMMIT() asm volatile("cp.async.commit_group;" ::: "memory")
#define CP_WAIT1()  asm volatile("cp.async.wait_group 1;" ::: "memory")

#define BUFW   1536
#define STAGES 3

// TF32 GEMM: block 128x128, k-tile 8, 4 warps (2x2), warp tile 64x64,
// 3-stage cp.async pipeline, pre-rounded tf32 operands (no consumer cvt),
// single barrier per k-tile, split-K + causal modes.
__global__ __launch_bounds__(128) void tgemm(GP p) {
    int bmI = blockIdx.y, bnI = blockIdx.x;
    if (p.mode == 1 && bnI > bmI) return;

    int z = blockIdx.z;
    int zb = z / p.kSplit;
    int kz = z % p.kSplit;

    int kTot = p.K;
    if (p.mode == 2) { int ke = (bmI + 1) * 128; if (ke < kTot) kTot = ke; }
    int kLen = kTot / p.kSplit;

    const float* A = p.A + (long)(zb / p.aDiv) * p.aS1 + (long)(zb % p.aMod) * p.aS2
                   + (long)kz * kLen * p.sAk;
    const float* B = p.B + (long)(zb / p.bDiv) * p.bS1 + (long)(zb % p.bMod) * p.bS2
                   + (long)kz * kLen * p.sBk;
    float*       C = p.C + (long)(zb / p.cDiv) * p.cS1 + (long)(zb % p.cMod) * p.cS2;

    __shared__ __align__(16) float As[STAGES][BUFW];
    __shared__ __align__(16) float Bs[STAGES][BUFW];

    int tid  = threadIdx.x;
    int lane = tid & 31;
    int wid  = tid >> 5;
    int wm = wid >> 1, wn = wid & 1;
    int bm = bmI * 128, bn = bnI * 128;

    const bool aKc = (p.sAk == 1);
    const bool bKc = (p.sBk == 1);

    const unsigned SaM = aKc ? 12u : 1u,  SaK = aKc ? 1u : 136u;
    const unsigned SbN = bKc ? 12u : 1u,  SbK = bKc ? 1u : 136u;

    const float* aBase;  long aStep;  unsigned aOff;
    if (aKc) {
        aBase = A + (long)(bm + tid) * p.sAm;
        aStep = 8;
        aOff  = tid * 12;
    } else {
        int k8 = tid >> 4, m0 = (tid & 15) * 8;
        aBase = A + (long)k8 * p.sAk + (bm + m0);
        aStep = 8 * p.sAk;
        aOff  = k8 * 136 + m0;
    }
    const float* bBase;  long bStep;  unsigned bOff;  bool bOk;
    if (bKc) {
        bOk = (bn + tid) < p.N;
        bBase = B + (long)(bn + tid) * p.sBn;
        bStep = 8;
        bOff  = tid * 12;
    } else {
        int k8 = tid >> 4, n0 = (tid & 15) * 8;
        bOk = (bn + n0) < p.N;
        bBase = B + (long)k8 * p.sBk + (bn + n0);
        bStep = 8 * p.sBk;
        bOff  = k8 * 136 + n0;
    }

    unsigned aSm[STAGES], bSm[STAGES];
#pragma unroll
    for (int s = 0; s < STAGES; s++) {
        aSm[s] = (unsigned)__cvta_generic_to_shared(&As[s][aOff]);
        bSm[s] = (unsigned)__cvta_generic_to_shared(&Bs[s][bOff]);
    }

#define FETCH(t, slot)                                                       \
    do {                                                                     \
        const float* ap = aBase + (long)(t) * aStep;                         \
        CP16(aSm[slot],      ap);                                            \
        CP16(aSm[slot] + 16, ap + 4);                                        \
        if (bOk) {                                                           \
            const float* bp = bBase + (long)(t) * bStep;                     \
            CP16(bSm[slot],      bp);                                        \
            CP16(bSm[slot] + 16, bp + 4);                                    \
        }                                                                    \
        CP_COMMIT();                                                         \
    } while (0)

    float acc[4][8][4];
#pragma unroll
    for (int i = 0; i < 4; i++)
#pragma unroll
        for (int j = 0; j < 8; j++)
#pragma unroll
            for (int r = 0; r < 4; r++) acc[i][j][r] = 0.f;

    int nt = kLen >> 3;

    FETCH(0, 0);
    if (nt > 1) {
        FETCH(1, 1);
    } else {
        CP_COMMIT();
    }

    int r = lane >> 2, c = lane & 3;

    unsigned aAddr[4], bAddr[8];
#pragma unroll
    for (int mi = 0; mi < 4; mi++)
        aAddr[mi] = (unsigned)(wm * 64 + mi * 16 + r) * SaM + (unsigned)c * SaK;
#pragma unroll
    for (int ni = 0; ni < 8; ni++)
        bAddr[ni] = (unsigned)(wn * 64 + ni * 8 + r) * SbN + (unsigned)c * SbK;
    const unsigned a8 = 8u * SaM, a4k = 4u * SaK, b4k = 4u * SbK;

    int slot = 0;
    for (int t = 0; t < nt; t++) {
        CP_WAIT1();            // group t complete (<=1 pending)
        __syncthreads();       // visibility + slot-reuse fence (see note)

        // refill slot (t+2)%3 early: all warps already finished reading it
        // (it was iteration t-1's compute slot, fenced by the barrier above)
        if (t + 2 < nt) {
            int ns = slot + 2; if (ns >= STAGES) ns -= STAGES;
            FETCH(t + 2, ns);
        } else {
            CP_COMMIT();
        }

        const unsigned* sa = (const unsigned*)&As[slot][0];
        const unsigned* sb = (const unsigned*)&Bs[slot][0];
        unsigned a[4][4], b[8][2];
#pragma unroll
        for (int mi = 0; mi < 4; mi++) {
            unsigned o = aAddr[mi];
            a[mi][0] = sa[o];
            a[mi][1] = sa[o + a8];
            a[mi][2] = sa[o + a4k];
            a[mi][3] = sa[o + a8 + a4k];
        }
#pragma unroll
        for (int ni = 0; ni < 8; ni++) {
            unsigned o = bAddr[ni];
            b[ni][0] = sb[o];
            b[ni][1] = sb[o + b4k];
        }
#pragma unroll
        for (int mi = 0; mi < 4; mi++)
#pragma unroll
            for (int ni = 0; ni < 8; ni++)
                mma_tf32(acc[mi][ni], a[mi], b[ni]);

        if (++slot == STAGES) slot = 0;
    }

    int c2 = (lane & 3) * 2;
    if (p.kSplit > 1) {
#pragma unroll
        for (int mi = 0; mi < 4; mi++) {
            int gm0 = bm + wm * 64 + mi * 16 + r;
#pragma unroll
            for (int ni = 0; ni < 8; ni++) {
                int gn = bn + wn * 64 + ni * 8 + c2;
                if (gn < p.N) {
                    atomicAdd(C + (long)gm0 * p.ldc + gn,     acc[mi][ni][0]);
                    atomicAdd(C + (long)gm0 * p.ldc + gn + 1, acc[mi][ni][1]);
                    atomicAdd(C + (long)(gm0 + 8) * p.ldc + gn,     acc[mi][ni][2]);
                    atomicAdd(C + (long)(gm0 + 8) * p.ldc + gn + 1, acc[mi][ni][3]);
                }
            }
        }
    } else if (p.roundC) {
#pragma unroll
        for (int mi = 0; mi < 4; mi++) {
            int gm0 = bm + wm * 64 + mi * 16 + r;
#pragma unroll
            for (int ni = 0; ni < 8; ni++) {
                int gn = bn + wn * 64 + ni * 8 + c2;
                if (gn < p.N) {
                    float* cp0 = C + (long)gm0 * p.ldc + gn;
                    float* cp1 = C + (long)(gm0 + 8) * p.ldc + gn;
                    cp0[0] = __uint_as_float(f2tf32(acc[mi][ni][0]));
                    cp0[1] = __uint_as_float(f2tf32(acc[mi][ni][1]));
                    cp1[0] = __uint_as_float(f2tf32(acc[mi][ni][2]));
                    cp1[1] = __uint_as_float(f2tf32(acc[mi][ni][3]));
                }
            }
        }
    } else {
#pragma unroll
        for (int mi = 0; mi < 4; mi++) {
            int gm0 = bm + wm * 64 + mi * 16 + r;
#pragma unroll
            for (int ni = 0; ni < 8; ni++) {
                int gn = bn + wn * 64 + ni * 8 + c2;
                if (gn < p.N) {
                    float* cp0 = C + (long)gm0 * p.ldc + gn;
                    float* cp1 = C + (long)(gm0 + 8) * p.ldc + gn;
                    cp0[0] = acc[mi][ni][0]; cp0[1] = acc[mi][ni][1];
                    cp1[0] = acc[mi][ni][2]; cp1[1] = acc[mi][ni][3];
                }
            }
        }
    }
#undef FETCH
}

// ---------------- tf32 rounding passes ----------------
__global__ void round_copy(const float* __restrict__ s, float* __restrict__ d,
                           long n) {
    long i = ((long)blockIdx.x * blockDim.x + threadIdx.x) * 4;
    if (i < n) {
        float4 v = *(const float4*)(s + i);
        v.x = __uint_as_float(f2tf32(v.x));
        v.y = __uint_as_float(f2tf32(v.y));
        v.z = __uint_as_float(f2tf32(v.z));
        v.w = __uint_as_float(f2tf32(v.w));
        *(float4*)(d + i) = v;
    }
}

// ---------------- RoPE ----------------
__global__ void rope_k_kernel(const float* __restrict__ ckr,
                              const float* __restrict__ fc,
                              const float* __restrict__ fs,
                              float* __restrict__ kcat) {
    int idx = blockIdx.x * blockDim.x + threadIdx.x;
    if (idx >= 2048 * 32) return;
    int m = idx >> 5, i = idx & 31;
    int t = m & 1023;
    float re = ckr[m * 64 + 2 * i], im = ckr[m * 64 + 2 * i + 1];
    float c = fc[t * 32 + i], s = fs[t * 32 + i];
    long o = (long)m * KCAT + 512 + 2 * i;
    kcat[o]     = re * c - im * s;
    kcat[o + 1] = re * s + im * c;
}

__global__ void rope_q_kernel(const float* __restrict__ cqr,
                              const float* __restrict__ fc,
                              const float* __restrict__ fs,
                              float* __restrict__ qcat) {
    int idx = blockIdx.x * blockDim.x + threadIdx.x;
    if (idx >= 2048 * 16 * 32) return;
    int i = idx & 31;
    int h = (idx >> 5) & 15;
    int m = idx >> 9;
    int t = m & 1023, b = m >> 10;
    float re = cqr[m * 1024 + h * 64 + 2 * i];
    float im = cqr[m * 1024 + h * 64 + 2 * i + 1];
    float c = fc[t * 32 + i], s = fs[t * 32 + i];
    long o = ((long)((b * 16 + h) * 1024 + t)) * KCAT + 512 + 2 * i;
    qcat[o]     = __uint_as_float(f2tf32(re * c - im * s));
    qcat[o + 1] = __uint_as_float(f2tf32(re * s + im * c));
}

// ---------------- causal softmax (tf32-rounded output) ----------------
__global__ void softmax_causal(float* __restrict__ attn) {
    int t = blockIdx.x;
    int z = blockIdx.y;
    float* p = attn + (long)z * 1024 * 1024 + (long)t * 1024;
    int n = t + 1;
    int lim = ((t >> 7) + 1) << 7;
    const float scale = 0.07216878364870322992f * 1.44269504088896341f;
    __shared__ float red[256];
    int tid = threadIdx.x;

    float vals[4];
    float m = -3.4e38f;
#pragma unroll
    for (int j = 0; j < 4; j++) {
        int s = tid + j * 256;
        vals[j] = (s < n) ? p[s] * scale : -3.4e38f;
        m = fmaxf(m, vals[j]);
    }
    red[tid] = m; __syncthreads();
    for (int o = 128; o > 0; o >>= 1) {
        if (tid < o) red[tid] = fmaxf(red[tid], red[tid + o]);
        __syncthreads();
    }
    m = red[0]; __syncthreads();

    float sum = 0.f;
#pragma unroll
    for (int j = 0; j < 4; j++) {
        int s = tid + j * 256;
        vals[j] = (s < n) ? exp2f(vals[j] - m) : 0.f;
        sum += vals[j];
    }
    red[tid] = sum; __syncthreads();
    for (int o = 128; o > 0; o >>= 1) {
        if (tid < o) red[tid] += red[tid + o];
        __syncthreads();
    }
    float inv = 1.f / red[0];

#pragma unroll
    for (int j = 0; j < 4; j++) {
        int s = tid + j * 256;
        if (s < lim) p[s] = __uint_as_float(f2tf32(vals[j] * inv));
    }
}

// ---------------- launch helper ----------------
static void launch_gemm(const float* A, const float* B, float* C,
                        int M, int N, int K,
                        long sAm, long sAk, long sBk, long sBn, long ldc,
                        int batches,
                        int aDiv, long aS1, int aMod, long aS2,
                        int bDiv, long bS1, int bMod, long bS2,
                        int cDiv, long cS1, int cMod, long cS2,
                        int kSplit = 1, int mode = 0, int roundC = 0) {
    GP p;
    p.A = A; p.B = B; p.C = C;
    p.M = M; p.N = N; p.K = K;
    p.sAm = sAm; p.sAk = sAk; p.sBk = sBk; p.sBn = sBn; p.ldc = ldc;
    p.aDiv = aDiv; p.aMod = aMod; p.bDiv = bDiv; p.bMod = bMod;
    p.cDiv = cDiv; p.cMod = cMod;
    p.aS1 = aS1; p.aS2 = aS2; p.bS1 = bS1; p.bS2 = bS2; p.cS1 = cS1; p.cS2 = cS2;
    p.kSplit = kSplit; p.mode = mode; p.roundC = roundC;
    dim3 grid((N + 127) / 128, (M + 127) / 128, batches * kSplit);
    tgemm<<<grid, 128>>>(p);
}

static void launch_round(const float* s, float* d, long n) {
    round_copy<<<(unsigned)((n / 4 + 255) / 256), 256>>>(s, d, n);
}

extern "C" void kernel_launch(void* const* d_in, const int* in_sizes, int n_in,
                              void* d_out, int out_size) {
    const float* x     = (const float*)d_in[0];
    const float* fcos  = (const float*)d_in[1];
    const float* fsin  = (const float*)d_in[2];
    const float* W_dq  = (const float*)d_in[3];
    const float* W_uq  = (const float*)d_in[4];
    const float* W_dkv = (const float*)d_in[5];
    const float* W_uk  = (const float*)d_in[6];
    const float* W_uv  = (const float*)d_in[7];
    const float* W_qr  = (const float*)d_in[8];
    const float* W_kr  = (const float*)d_in[9];
    const float* W_o   = (const float*)d_in[10];
    float* out = (float*)d_out;

    float *keff, *veff, *cq, *ckr, *cqr, *kcat, *qcat, *attn, *lat, *wb;
    cudaGetSymbolAddress((void**)&keff, g_keff);
    cudaGetSymbolAddress((void**)&veff, g_veff);
    cudaGetSymbolAddress((void**)&cq,   g_cq);
    cudaGetSymbolAddress((void**)&ckr,  g_ckr);
    cudaGetSymbolAddress((void**)&cqr,  g_cqr);
    cudaGetSymbolAddress((void**)&kcat, g_kcat);
    cudaGetSymbolAddress((void**)&qcat, g_qcat);
    cudaGetSymbolAddress((void**)&attn, g_attn);
    cudaGetSymbolAddress((void**)&lat,  g_lat);
    cudaGetSymbolAddress((void**)&wb,   g_wbuf);

    float* xr   = wb + OFF_X;
    float* wdq  = wb + OFF_WDQ;
    float* wdkv = wb + OFF_WDKV;
    float* wuk  = wb + OFF_WUK;
    float* wuq  = wb + OFF_WUQ;
    float* wuv  = wb + OFF_WUV;
    float* wqr  = wb + OFF_WQR;
    float* wkr  = wb + OFF_WKR;
    float* wo   = wb + OFF_WO;

    cudaMemsetAsync(veff, 0, 2048l * 512 * 4);
    cudaMemsetAsync(cq,   0, 2048l * 512 * 4);
    cudaMemsetAsync(ckr,  0, 2048l * 64 * 4);
    cudaMemsetAsync(cqr,  0, 2048l * 1024 * 4);
    cudaMemsetAsync(kcat, 0, 2048l * 576 * 4);

    // 0) tf32-round external inputs once
    launch_round(x,     xr,   4194304);
    launch_round(W_dq,  wdq,  1048576);
    launch_round(W_dkv, wdkv, 1048576);
    launch_round(W_uk,  wuk,  1048576);
    launch_round(W_uq,  wuq,  1048576);
    launch_round(W_uv,  wuv,  1048576);
    launch_round(W_qr,  wqr,  524288);
    launch_round(W_kr,  wkr,  131072);
    launch_round(W_o,   wo,   4194304);

    // 1) keff_t[h][k][q]  (rounded epilogue)
    launch_gemm(wuk, wuq, keff, 512, 512, 128,
                1, 512, 1, 2048, 512, 16,
                1, 0, 16, 128l * 512,
                1, 0, 16, 128,
                1, 0, 16, 512l * 512, 1, 0, 1);

    // 2) veff_t[j][k]  (split-K 4, then round)
    launch_gemm(wo, wuv, veff, 2048, 512, 2048,
                2048, 1, 512, 1, 512, 1,
                1, 0, 1, 0, 1, 0, 1, 0, 1, 0, 1, 0, 4);
    launch_round(veff, veff, 1048576);

    // 3) c_q  (split-K 4, then round)
    launch_gemm(xr, wdq, cq, 2048, 512, 2048,
                2048, 1, 1, 2048, 512, 1,
                1, 0, 1, 0, 1, 0, 1, 0, 1, 0, 1, 0, 4);
    launch_round(cq, cq, 1048576);

    // 4) c_kv -> kcat cols [0,512)  (split-K 4)
    launch_gemm(xr, wdkv, kcat, 2048, 512, 2048,
                2048, 1, 1, 2048, KCAT, 1,
                1, 0, 1, 0, 1, 0, 1, 0, 1, 0, 1, 0, 4);

    // 5) c_kr  (split-K 8)
    launch_gemm(xr, wkr, ckr, 2048, 64, 2048,
                2048, 1, 1, 2048, 64, 1,
                1, 0, 1, 0, 1, 0, 1, 0, 1, 0, 1, 0, 8);

    // 6) c_qr  (split-K 2; feeds rope only, no rounding needed)
    launch_gemm(cq, wqr, cqr, 2048, 1024, 512,
                512, 1, 1, 512, 1024, 1,
                1, 0, 1, 0, 1, 0, 1, 0, 1, 0, 1, 0, 2);

    // 7) RoPE k -> kcat cols [512,576), then round whole kcat
    rope_k_kernel<<<(2048 * 32 + 255) / 256, 256>>>(ckr, fcos, fsin, kcat);
    launch_round(kcat, kcat, 2048l * 576);

    // 8) RoPE q (rounds on write)
    rope_q_kernel<<<(2048 * 16 * 32 + 255) / 256, 256>>>(cqr, fcos, fsin, qcat);

    // 9) q_abs (rounded epilogue)
    launch_gemm(cq, keff, qcat, 1024, 512, 512,
                512, 1, 1, 512, KCAT, 32,
                16, 1024l * 512, 1, 0,
                1, 0, 16, 512l * 512,
                1, 0, 32, 1024l * KCAT, 1, 0, 1);

    // 10) logits (causal tile-skip; raw fp32 out, softmax rounds)
    launch_gemm(qcat, kcat, attn, 1024, 1024, KCAT,
                KCAT, 1, 1, KCAT, 1024, 32,
                1, 0, 32, 1024l * KCAT,
                16, 1024l * KCAT, 1, 0,
                1, 0, 32, 1024l * 1024, 1, 1);

    // 11) softmax (rounds output)
    {
        dim3 grid(1024, 32);
        softmax_causal<<<grid, 256>>>(attn);
    }

    // 12) lat (causal k-stop, rounded epilogue)
    launch_gemm(attn, kcat, lat, 1024, 512, 1024,
                1024, 1, KCAT, 1, 512, 32,
                1, 0, 32, 1024l * 1024,
                16, 1024l * KCAT, 1, 0,
                1, 0, 32, 1024l * 512, 1, 2, 1);

    // 13) y = lat @ veff_t^T  (raw fp32 output)
    launch_gemm(lat, veff, out, 1024, 128, 512,
                512, 1, 1, 512, 2048, 32,
                1, 0, 32, 1024l * 512,
                1, 0, 16, 128l * 512,
                16, 1024l * 2048, 16, 128);
}

// round 13
// speedup vs baseline: 1.0939x; 1.0939x over previous
#include <cuda_runtime.h>
#include <cuda_bf16.h>
#include <math.h>

#define BB   2
#define TT   1024
#define CC   2048
#define NH   16
#define HS   128
#define NLQ  512
#define NLKV 512
#define DHR  64
#define KCAT 576

// ---------------- scratch ----------------
__device__ float g_keff[16l * 512 * 512];       // keff_t[h][k][q] (q contiguous)
__device__ float g_veff[2048l * 512];           // veff_t[j][k]   (k contiguous)
__device__ float g_cq  [2048l * 512];
__device__ float g_ckr [2048l * 64];
__device__ float g_cqr [2048l * 1024];
__device__ float g_kcat[2048l * 576];
__device__ float g_qcat[32l * 1024 * 576];
__device__ float g_attn[32l * 1024 * 1024];
__device__ float g_lat [32l * 1024 * 512];

struct GP {
    const float* A; const float* B; float* C;
    int M, N, K;
    long sAm, sAk, sBk, sBn, ldc;
    int aDiv, aMod, bDiv, bMod, cDiv, cMod;
    long aS1, aS2, bS1, bS2, cS1, cS2;
    int kSplit;
    int mode;    // 0 plain, 1 causal tile-skip, 2 causal k-stop
};

__device__ __forceinline__ unsigned f2tf32(float x) {
    unsigned u;
    asm("cvt.rna.tf32.f32 %0, %1;" : "=r"(u) : "f"(x));
    return u;
}

__device__ __forceinline__ void mma_tf32(float* d, const unsigned* a,
                                         const unsigned* b) {
    asm volatile(
        "mma.sync.aligned.m16n8k8.row.col.f32.tf32.tf32.f32 "
        "{%0,%1,%2,%3}, {%4,%5,%6,%7}, {%8,%9}, {%0,%1,%2,%3};\n"
        : "+f"(d[0]), "+f"(d[1]), "+f"(d[2]), "+f"(d[3])
        : "r"(a[0]), "r"(a[1]), "r"(a[2]), "r"(a[3]),
          "r"(b[0]), "r"(b[1]));
}

#define CP16(dst, src) \
    asm volatile("cp.async.cg.shared.global [%0], [%1], 16;" \
                 :: "r"(dst), "l"(src))
#define CP_COMMIT() asm volatile("cp.async.commit_group;" ::: "memory")
#define CP_WAIT1()  asm volatile("cp.async.wait_group 1;" ::: "memory")

#define BUFW   1536
#define STAGES 3

// TF32 GEMM: block 128x128, k-tile 8, 4 warps (2x2), warp tile 64x64,
// 3-stage cp.async pipeline, consumer-side tf32 cvt, single barrier/tile,
// split-K + causal modes.
__global__ __launch_bounds__(128) void tgemm(GP p) {
    int bmI = blockIdx.y, bnI = blockIdx.x;
    if (p.mode == 1 && bnI > bmI) return;

    int z = blockIdx.z;
    int zb = z / p.kSplit;
    int kz = z % p.kSplit;

    int kTot = p.K;
    if (p.mode == 2) { int ke = (bmI + 1) * 128; if (ke < kTot) kTot = ke; }
    int kLen = kTot / p.kSplit;

    const float* A = p.A + (long)(zb / p.aDiv) * p.aS1 + (long)(zb % p.aMod) * p.aS2
                   + (long)kz * kLen * p.sAk;
    const float* B = p.B + (long)(zb / p.bDiv) * p.bS1 + (long)(zb % p.bMod) * p.bS2
                   + (long)kz * kLen * p.sBk;
    float*       C = p.C + (long)(zb / p.cDiv) * p.cS1 + (long)(zb % p.cMod) * p.cS2;

    __shared__ __align__(16) float As[STAGES][BUFW];
    __shared__ __align__(16) float Bs[STAGES][BUFW];

    int tid  = threadIdx.x;
    int lane = tid & 31;
    int wid  = tid >> 5;
    int wm = wid >> 1, wn = wid & 1;
    int bm = bmI * 128, bn = bnI * 128;

    const bool aKc = (p.sAk == 1);
    const bool bKc = (p.sBk == 1);

    const unsigned SaM = aKc ? 12u : 1u,  SaK = aKc ? 1u : 136u;
    const unsigned SbN = bKc ? 12u : 1u,  SbK = bKc ? 1u : 136u;

    const float* aBase;  long aStep;  unsigned aOff;
    if (aKc) {
        aBase = A + (long)(bm + tid) * p.sAm;
        aStep = 8;
        aOff  = tid * 12;
    } else {
        int k8 = tid >> 4, m0 = (tid & 15) * 8;
        aBase = A + (long)k8 * p.sAk + (bm + m0);
        aStep = 8 * p.sAk;
        aOff  = k8 * 136 + m0;
    }
    const float* bBase;  long bStep;  unsigned bOff;  bool bOk;
    if (bKc) {
        bOk = (bn + tid) < p.N;
        bBase = B + (long)(bn + tid) * p.sBn;
        bStep = 8;
        bOff  = tid * 12;
    } else {
        int k8 = tid >> 4, n0 = (tid & 15) * 8;
        bOk = (bn + n0) < p.N;
        bBase = B + (long)k8 * p.sBk + (bn + n0);
        bStep = 8 * p.sBk;
        bOff  = k8 * 136 + n0;
    }

    unsigned aSm[STAGES], bSm[STAGES];
#pragma unroll
    for (int s = 0; s < STAGES; s++) {
        aSm[s] = (unsigned)__cvta_generic_to_shared(&As[s][aOff]);
        bSm[s] = (unsigned)__cvta_generic_to_shared(&Bs[s][bOff]);
    }

#define FETCH(t, slot)                                                       \
    do {                                                                     \
        const float* ap = aBase + (long)(t) * aStep;                         \
        CP16(aSm[slot],      ap);                                            \
        CP16(aSm[slot] + 16, ap + 4);                                        \
        if (bOk) {                                                           \
            const float* bp = bBase + (long)(t) * bStep;                     \
            CP16(bSm[slot],      bp);                                        \
            CP16(bSm[slot] + 16, bp + 4);                                    \
        }                                                                    \
        CP_COMMIT();                                                         \
    } while (0)

    float acc[4][8][4];
#pragma unroll
    for (int i = 0; i < 4; i++)
#pragma unroll
        for (int j = 0; j < 8; j++)
#pragma unroll
            for (int r = 0; r < 4; r++) acc[i][j][r] = 0.f;

    int nt = kLen >> 3;

    FETCH(0, 0);
    if (nt > 1) {
        FETCH(1, 1);
    } else {
        CP_COMMIT();
    }

    int r = lane >> 2, c = lane & 3;

    unsigned aAddr[4], bAddr[8];
#pragma unroll
    for (int mi = 0; mi < 4; mi++)
        aAddr[mi] = (unsigned)(wm * 64 + mi * 16 + r) * SaM + (unsigned)c * SaK;
#pragma unroll
    for (int ni = 0; ni < 8; ni++)
        bAddr[ni] = (unsigned)(wn * 64 + ni * 8 + r) * SbN + (unsigned)c * SbK;
    const unsigned a8 = 8u * SaM, a4k = 4u * SaK, b4k = 4u * SbK;

    int slot = 0;
    for (int t = 0; t < nt; t++) {
        CP_WAIT1();            // group t complete (<=1 pending)
        __syncthreads();       // visibility + slot-reuse fence

        // refill slot (t+2)%3 early: it was iteration t-1's compute slot,
        // all warps finished reading it before the barrier above
        if (t + 2 < nt) {
            int ns = slot + 2; if (ns >= STAGES) ns -= STAGES;
            FETCH(t + 2, ns);
        } else {
            CP_COMMIT();
        }

        const float* sa = &As[slot][0];
        const float* sb = &Bs[slot][0];
        unsigned a[4][4], b[8][2];
#pragma unroll
        for (int mi = 0; mi < 4; mi++) {
            unsigned o = aAddr[mi];
            a[mi][0] = f2tf32(sa[o]);
            a[mi][1] = f2tf32(sa[o + a8]);
            a[mi][2] = f2tf32(sa[o + a4k]);
            a[mi][3] = f2tf32(sa[o + a8 + a4k]);
        }
#pragma unroll
        for (int ni = 0; ni < 8; ni++) {
            unsigned o = bAddr[ni];
            b[ni][0] = f2tf32(sb[o]);
            b[ni][1] = f2tf32(sb[o + b4k]);
        }
#pragma unroll
        for (int mi = 0; mi < 4; mi++)
#pragma unroll
            for (int ni = 0; ni < 8; ni++)
                mma_tf32(acc[mi][ni], a[mi], b[ni]);

        if (++slot == STAGES) slot = 0;
    }

    int c2 = (lane & 3) * 2;
    if (p.kSplit > 1) {
#pragma unroll
        for (int mi = 0; mi < 4; mi++) {
            int gm0 = bm + wm * 64 + mi * 16 + r;
#pragma unroll
            for (int ni = 0; ni < 8; ni++) {
                int gn = bn + wn * 64 + ni * 8 + c2;
                if (gn < p.N) {
                    atomicAdd(C + (long)gm0 * p.ldc + gn,     acc[mi][ni][0]);
                    atomicAdd(C + (long)gm0 * p.ldc + gn + 1, acc[mi][ni][1]);
                    atomicAdd(C + (long)(gm0 + 8) * p.ldc + gn,     acc[mi][ni][2]);
                    atomicAdd(C + (long)(gm0 + 8) * p.ldc + gn + 1, acc[mi][ni][3]);
                }
            }
        }
    } else {
#pragma unroll
        for (int mi = 0; mi < 4; mi++) {
            int gm0 = bm + wm * 64 + mi * 16 + r;
#pragma unroll
            for (int ni = 0; ni < 8; ni++) {
                int gn = bn + wn * 64 + ni * 8 + c2;
                if (gn < p.N) {
                    float* cp0 = C + (long)gm0 * p.ldc + gn;
                    float* cp1 = C + (long)(gm0 + 8) * p.ldc + gn;
                    cp0[0] = acc[mi][ni][0]; cp0[1] = acc[mi][ni][1];
                    cp1[0] = acc[mi][ni][2]; cp1[1] = acc[mi][ni][3];
                }
            }
        }
    }
#undef FETCH
}

// ---------------- RoPE ----------------
__global__ void rope_k_kernel(const float* __restrict__ ckr,
                              const float* __restrict__ fc,
                              const float* __restrict__ fs,
                              float* __restrict__ kcat) {
    int idx = blockIdx.x * blockDim.x + threadIdx.x;
    if (idx >= 2048 * 32) return;
    int m = idx >> 5, i = idx & 31;
    int t = m & 1023;
    float re = ckr[m * 64 + 2 * i], im = ckr[m * 64 + 2 * i + 1];
    float c = fc[t * 32 + i], s = fs[t * 32 + i];
    long o = (long)m * KCAT + 512 + 2 * i;
    kcat[o]     = re * c - im * s;
    kcat[o + 1] = re * s + im * c;
}

__global__ void rope_q_kernel(const float* __restrict__ cqr,
                              const float* __restrict__ fc,
                              const float* __restrict__ fs,
                              float* __restrict__ qcat) {
    int idx = blockIdx.x * blockDim.x + threadIdx.x;
    if (idx >= 2048 * 16 * 32) return;
    int i = idx & 31;
    int h = (idx >> 5) & 15;
    int m = idx >> 9;
    int t = m & 1023, b = m >> 10;
    float re = cqr[m * 1024 + h * 64 + 2 * i];
    float im = cqr[m * 1024 + h * 64 + 2 * i + 1];
    float c = fc[t * 32 + i], s = fs[t * 32 + i];
    long o = ((long)((b * 16 + h) * 1024 + t)) * KCAT + 512 + 2 * i;
    qcat[o]     = re * c - im * s;
    qcat[o + 1] = re * s + im * c;
}

// ---------------- causal softmax (shuffle reductions) ----------------
__global__ void softmax_causal(float* __restrict__ attn) {
    int t = blockIdx.x;
    int z = blockIdx.y;
    float* p = attn + (long)z * 1024 * 1024 + (long)t * 1024;
    int n = t + 1;
    int lim = ((t >> 7) + 1) << 7;
    const float scale = 0.07216878364870322992f * 1.44269504088896341f;
    __shared__ float red[8];
    int tid = threadIdx.x;
    int lane = tid & 31, w = tid >> 5;

    float vals[4];
    float m = -3.4e38f;
#pragma unroll
    for (int j = 0; j < 4; j++) {
        int s = tid + j * 256;
        vals[j] = (s < n) ? p[s] * scale : -3.4e38f;
        m = fmaxf(m, vals[j]);
    }
#pragma unroll
    for (int o = 16; o > 0; o >>= 1)
        m = fmaxf(m, __shfl_xor_sync(0xffffffffu, m, o));
    if (lane == 0) red[w] = m;
    __syncthreads();
    {
        float mm = red[lane & 7];
#pragma unroll
        for (int o = 4; o > 0; o >>= 1)
            mm = fmaxf(mm, __shfl_xor_sync(0xffffffffu, mm, o));
        m = mm;
    }
    __syncthreads();

    float sum = 0.f;
#pragma unroll
    for (int j = 0; j < 4; j++) {
        int s = tid + j * 256;
        vals[j] = (s < n) ? exp2f(vals[j] - m) : 0.f;
        sum += vals[j];
    }
#pragma unroll
    for (int o = 16; o > 0; o >>= 1)
        sum += __shfl_xor_sync(0xffffffffu, sum, o);
    if (lane == 0) red[w] = sum;
    __syncthreads();
    {
        float ss = red[lane & 7];
#pragma unroll
        for (int o = 4; o > 0; o >>= 1)
            ss += __shfl_xor_sync(0xffffffffu, ss, o);
        sum = ss;
    }
    float inv = 1.f / sum;

#pragma unroll
    for (int j = 0; j < 4; j++) {
        int s = tid + j * 256;
        if (s < lim) p[s] = vals[j] * inv;
    }
}

// ---------------- launch helper ----------------
static void launch_gemm(const float* A, const float* B, float* C,
                        int M, int N, int K,
                        long sAm, long sAk, long sBk, long sBn, long ldc,
                        int batches,
                        int aDiv, long aS1, int aMod, long aS2,
                        int bDiv, long bS1, int bMod, long bS2,
                        int cDiv, long cS1, int cMod, long cS2,
                        int kSplit = 1, int mode = 0) {
    GP p;
    p.A = A; p.B = B; p.C = C;
    p.M = M; p.N = N; p.K = K;
    p.sAm = sAm; p.sAk = sAk; p.sBk = sBk; p.sBn = sBn; p.ldc = ldc;
    p.aDiv = aDiv; p.aMod = aMod; p.bDiv = bDiv; p.bMod = bMod;
    p.cDiv = cDiv; p.cMod = cMod;
    p.aS1 = aS1; p.aS2 = aS2; p.bS1 = bS1; p.bS2 = bS2; p.cS1 = cS1; p.cS2 = cS2;
    p.kSplit = kSplit; p.mode = mode;
    dim3 grid((N + 127) / 128, (M + 127) / 128, batches * kSplit);
    tgemm<<<grid, 128>>>(p);
}

extern "C" void kernel_launch(void* const* d_in, const int* in_sizes, int n_in,
                              void* d_out, int out_size) {
    const float* x     = (const float*)d_in[0];
    const float* fcos  = (const float*)d_in[1];
    const float* fsin  = (const float*)d_in[2];
    const float* W_dq  = (const float*)d_in[3];
    const float* W_uq  = (const float*)d_in[4];
    const float* W_dkv = (const float*)d_in[5];
    const float* W_uk  = (const float*)d_in[6];
    const float* W_uv  = (const float*)d_in[7];
    const float* W_qr  = (const float*)d_in[8];
    const float* W_kr  = (const float*)d_in[9];
    const float* W_o   = (const float*)d_in[10];
    float* out = (float*)d_out;

    float *keff, *veff, *cq, *ckr, *cqr, *kcat, *qcat, *attn, *lat;
    cudaGetSymbolAddress((void**)&keff, g_keff);
    cudaGetSymbolAddress((void**)&veff, g_veff);
    cudaGetSymbolAddress((void**)&cq,   g_cq);
    cudaGetSymbolAddress((void**)&ckr,  g_ckr);
    cudaGetSymbolAddress((void**)&cqr,  g_cqr);
    cudaGetSymbolAddress((void**)&kcat, g_kcat);
    cudaGetSymbolAddress((void**)&qcat, g_qcat);
    cudaGetSymbolAddress((void**)&attn, g_attn);
    cudaGetSymbolAddress((void**)&lat,  g_lat);

    cudaMemsetAsync(veff, 0, 2048l * 512 * 4);
    cudaMemsetAsync(cq,   0, 2048l * 512 * 4);
    cudaMemsetAsync(ckr,  0, 2048l * 64 * 4);
    cudaMemsetAsync(cqr,  0, 2048l * 1024 * 4);
    cudaMemsetAsync(kcat, 0, 2048l * 576 * 4);

    // 1) keff_t[h][k][q]
    launch_gemm(W_uk, W_uq, keff, 512, 512, 128,
                1, 512, 1, 2048, 512, 16,
                1, 0, 16, 128l * 512,
                1, 0, 16, 128,
                1, 0, 16, 512l * 512);

    // 2) veff_t[j][k]  (split-K 8)
    launch_gemm(W_o, W_uv, veff, 2048, 512, 2048,
                2048, 1, 512, 1, 512, 1,
                1, 0, 1, 0, 1, 0, 1, 0, 1, 0, 1, 0, 8);

    // 3) c_q  (split-K 8)
    launch_gemm(x, W_dq, cq, 2048, 512, 2048,
                2048, 1, 1, 2048, 512, 1,
                1, 0, 1, 0, 1, 0, 1, 0, 1, 0, 1, 0, 8);

    // 4) c_kv -> kcat cols [0,512)  (split-K 8)
    launch_gemm(x, W_dkv, kcat, 2048, 512, 2048,
                2048, 1, 1, 2048, KCAT, 1,
                1, 0, 1, 0, 1, 0, 1, 0, 1, 0, 1, 0, 8);

    // 5) c_kr  (split-K 16)
    launch_gemm(x, W_kr, ckr, 2048, 64, 2048,
                2048, 1, 1, 2048, 64, 1,
                1, 0, 1, 0, 1, 0, 1, 0, 1, 0, 1, 0, 16);

    // 6) c_qr  (split-K 4)
    launch_gemm(cq, W_qr, cqr, 2048, 1024, 512,
                512, 1, 1, 512, 1024, 1,
                1, 0, 1, 0, 1, 0, 1, 0, 1, 0, 1, 0, 4);

    // 7-8) RoPE
    rope_k_kernel<<<(2048 * 32 + 255) / 256, 256>>>(ckr, fcos, fsin, kcat);
    rope_q_kernel<<<(2048 * 16 * 32 + 255) / 256, 256>>>(cqr, fcos, fsin, qcat);

    // 9) q_abs (B contiguous via keff_t)
    launch_gemm(cq, keff, qcat, 1024, 512, 512,
                512, 1, 1, 512, KCAT, 32,
                16, 1024l * 512, 1, 0,
                1, 0, 16, 512l * 512,
                1, 0, 32, 1024l * KCAT);

    // 10) logits (causal tile-skip)
    launch_gemm(qcat, kcat, attn, 1024, 1024, KCAT,
                KCAT, 1, 1, KCAT, 1024, 32,
                1, 0, 32, 1024l * KCAT,
                16, 1024l * KCAT, 1, 0,
                1, 0, 32, 1024l * 1024, 1, 1);

    // 11) softmax
    {
        dim3 grid(1024, 32);
        softmax_causal<<<grid, 256>>>(attn);
    }

    // 12) lat (causal k-stop)
    launch_gemm(attn, kcat, lat, 1024, 512, 1024,
                1024, 1, KCAT, 1, 512, 32,
                1, 0, 32, 1024l * 1024,
                16, 1024l * KCAT, 1, 0,
                1, 0, 32, 1024l * 512, 1, 2);

    // 13) y = lat @ veff_t^T
    launch_gemm(lat, veff, out, 1024, 128, 512,
                512, 1, 1, 512, 2048, 32,
                1, 0, 32, 1024l * 512,
                1, 0, 16, 128l * 512,
                16, 1024l * 2048, 16, 128);
}

// round 14
// speedup vs baseline: 1.6501x; 1.5084x over previous
#include <cuda_runtime.h>
#include <cuda_fp16.h>
#include <math.h>

#define BB   2
#define TT   1024
#define CC   2048
#define NH   16
#define HS   128
#define NLQ  512
#define NLKV 512
#define DHR  64
#define KCAT 576

// ---------------- fp32 scratch ----------------
__device__ float g_cq  [2048l * 512];
__device__ float g_ckr [2048l * 64];
__device__ float g_cqr [2048l * 1024];
__device__ float g_kcat[2048l * 576];
__device__ float g_veff[2048l * 512];
__device__ float g_attn[32l * 1024 * 1024];

// ---------------- fp16 scratch (all GEMM operands K-contiguous) ----------
__device__ __half h_x   [4194304];
__device__ __half h_wdq [1048576];
__device__ __half h_wdkv[1048576];
__device__ __half h_wkr [131072];
__device__ __half h_wqr [524288];
__device__ __half h_wo  [4194304];
__device__ __half h_wuq [1048576];
__device__ __half h_wukT[1048576];          // [h][k][d], d contiguous
__device__ __half h_wuvT[1048576];          // [k'][c], c contiguous
__device__ __half h_keff[16l * 512 * 512];  // keff_t[h][k][q], q contiguous
__device__ __half h_veff[2048l * 512];      // veff_t[j][k']
__device__ __half h_cq  [2048l * 512];
__device__ __half h_kcat[2048l * 576];
__device__ __half h_ckvt[2l * 512 * 1024];  // [b][k'][s], s contiguous
__device__ __half h_qcat[32l * 1024 * 576];
__device__ __half h_attn[32l * 1024 * 1024];
__device__ __half h_lat [32l * 1024 * 512];

struct GP {
    const __half* A; const __half* B; void* C;
    int M, N, K;
    long sA, sB, ldc;
    int aDiv, aMod, bDiv, bMod, cDiv, cMod;
    long aS1, aS2, bS1, bS2, cS1, cS2;
    int kSplit;
    int mode;    // 0 plain, 1 causal tile-skip, 2 causal k-stop
    int halfC;   // 1 -> C is __half*
};

__device__ __forceinline__ void mma_f16(float* d, const unsigned* a,
                                        const unsigned* b) {
    asm volatile(
        "mma.sync.aligned.m16n8k16.row.col.f32.f16.f16.f32 "
        "{%0,%1,%2,%3}, {%4,%5,%6,%7}, {%8,%9}, {%0,%1,%2,%3};\n"
        : "+f"(d[0]), "+f"(d[1]), "+f"(d[2]), "+f"(d[3])
        : "r"(a[0]), "r"(a[1]), "r"(a[2]), "r"(a[3]),
          "r"(b[0]), "r"(b[1]));
}

#define CP16(dst, src) \
    asm volatile("cp.async.cg.shared.global [%0], [%1], 16;" \
                 :: "r"(dst), "l"(src))
#define CP_COMMIT() asm volatile("cp.async.commit_group;" ::: "memory")
#define CP_WAIT1()  asm volatile("cp.async.wait_group 1;" ::: "memory")

#define SROW   24            // halves per smem row (bank-conflict free)
#define BUFW   (128 * SROW)  // 3072 halves per operand per stage
#define STAGES 3

// fp16 GEMM: block 128x128, k-tile 16, 4 warps (2x2), warp tile 64x64,
// 3-stage cp.async pipeline, all operands K-contiguous [row][k] fp16.
__global__ __launch_bounds__(128) void hgemm(GP p) {
    int bmI = blockIdx.y, bnI = blockIdx.x;
    if (p.mode == 1 && bnI > bmI) return;

    int z = blockIdx.z;
    int zb = z / p.kSplit;
    int kz = z % p.kSplit;

    int kTot = p.K;
    if (p.mode == 2) { int ke = (bmI + 1) * 128; if (ke < kTot) kTot = ke; }
    int kLen = kTot / p.kSplit;

    const __half* A = p.A + (long)(zb / p.aDiv) * p.aS1 + (long)(zb % p.aMod) * p.aS2
                    + (long)kz * kLen;
    const __half* B = p.B + (long)(zb / p.bDiv) * p.bS1 + (long)(zb % p.bMod) * p.bS2
                    + (long)kz * kLen;
    char* Cb = (char*)p.C;
    long cOff = (long)(zb / p.cDiv) * p.cS1 + (long)(zb % p.cMod) * p.cS2;

    __shared__ __align__(16) __half As[STAGES][BUFW];
    __shared__ __align__(16) __half Bs[STAGES][BUFW];

    int tid  = threadIdx.x;
    int lane = tid & 31;
    int wid  = tid >> 5;
    int wm = wid >> 1, wn = wid & 1;
    int bm = bmI * 128, bn = bnI * 128;

    const __half* aBase = A + (long)(bm + tid) * p.sA;
    bool bOk = (bn + tid) < p.N;
    const __half* bBase = B + (long)(bn + tid) * p.sB;

    unsigned aSm[STAGES], bSm[STAGES];
#pragma unroll
    for (int s = 0; s < STAGES; s++) {
        aSm[s] = (unsigned)__cvta_generic_to_shared(&As[s][tid * SROW]);
        bSm[s] = (unsigned)__cvta_generic_to_shared(&Bs[s][tid * SROW]);
    }

#define FETCH(t, slot)                                                       \
    do {                                                                     \
        const __half* ap = aBase + (long)(t) * 16;                           \
        CP16(aSm[slot],      ap);                                            \
        CP16(aSm[slot] + 16, ap + 8);                                        \
        if (bOk) {                                                           \
            const __half* bp = bBase + (long)(t) * 16;                       \
            CP16(bSm[slot],      bp);                                        \
            CP16(bSm[slot] + 16, bp + 8);                                    \
        }                                                                    \
        CP_COMMIT();                                                         \
    } while (0)

    float acc[4][8][4];
#pragma unroll
    for (int i = 0; i < 4; i++)
#pragma unroll
        for (int j = 0; j < 8; j++)
#pragma unroll
            for (int r = 0; r < 4; r++) acc[i][j][r] = 0.f;

    int nt = kLen >> 4;   // all kLen values divisible by 16

    FETCH(0, 0);
    if (nt > 1) {
        FETCH(1, 1);
    } else {
        CP_COMMIT();
    }

    int r = lane >> 2, c = lane & 3;

    // 32-bit fragment indices into smem (uint units): row*12 + c
    unsigned aAddr[4], bAddr[8];
#pragma unroll
    for (int mi = 0; mi < 4; mi++)
        aAddr[mi] = (unsigned)(wm * 64 + mi * 16 + r) * (SROW / 2) + (unsigned)c;
#pragma unroll
    for (int ni = 0; ni < 8; ni++)
        bAddr[ni] = (unsigned)(wn * 64 + ni * 8 + r) * (SROW / 2) + (unsigned)c;
    const unsigned aM8 = 8u * (SROW / 2);   // +8 rows (m)
    const unsigned k8  = 4u;                // +8 halves in k = +4 uints

    int slot = 0;
    for (int t = 0; t < nt; t++) {
        CP_WAIT1();
        __syncthreads();

        if (t + 2 < nt) {
            int ns = slot + 2; if (ns >= STAGES) ns -= STAGES;
            FETCH(t + 2, ns);
        } else {
            CP_COMMIT();
        }

        const unsigned* sa = (const unsigned*)&As[slot][0];
        const unsigned* sb = (const unsigned*)&Bs[slot][0];
        unsigned a[4][4], b[8][2];
#pragma unroll
        for (int mi = 0; mi < 4; mi++) {
            unsigned o = aAddr[mi];
            a[mi][0] = sa[o];            // (m,      k0..k0+1)
            a[mi][1] = sa[o + aM8];      // (m+8,    k0..k0+1)
            a[mi][2] = sa[o + k8];       // (m,      k0+8..9)
            a[mi][3] = sa[o + aM8 + k8]; // (m+8,    k0+8..9)
        }
#pragma unroll
        for (int ni = 0; ni < 8; ni++) {
            unsigned o = bAddr[ni];
            b[ni][0] = sb[o];
            b[ni][1] = sb[o + k8];
        }
#pragma unroll
        for (int mi = 0; mi < 4; mi++)
#pragma unroll
            for (int ni = 0; ni < 8; ni++)
                mma_f16(acc[mi][ni], a[mi], b[ni]);

        if (++slot == STAGES) slot = 0;
    }

    int c2 = (lane & 3) * 2;
    if (p.kSplit > 1) {
        float* C = (float*)Cb + cOff;
#pragma unroll
        for (int mi = 0; mi < 4; mi++) {
            int gm0 = bm + wm * 64 + mi * 16 + r;
#pragma unroll
            for (int ni = 0; ni < 8; ni++) {
                int gn = bn + wn * 64 + ni * 8 + c2;
                if (gn < p.N) {
                    atomicAdd(C + (long)gm0 * p.ldc + gn,     acc[mi][ni][0]);
                    atomicAdd(C + (long)gm0 * p.ldc + gn + 1, acc[mi][ni][1]);
                    atomicAdd(C + (long)(gm0 + 8) * p.ldc + gn,     acc[mi][ni][2]);
                    atomicAdd(C + (long)(gm0 + 8) * p.ldc + gn + 1, acc[mi][ni][3]);
                }
            }
        }
    } else if (p.halfC) {
        __half* C = (__half*)Cb + cOff;
#pragma unroll
        for (int mi = 0; mi < 4; mi++) {
            int gm0 = bm + wm * 64 + mi * 16 + r;
#pragma unroll
            for (int ni = 0; ni < 8; ni++) {
                int gn = bn + wn * 64 + ni * 8 + c2;
                if (gn < p.N) {
                    __half2 h0 = __floats2half2_rn(acc[mi][ni][0], acc[mi][ni][1]);
                    __half2 h1 = __floats2half2_rn(acc[mi][ni][2], acc[mi][ni][3]);
                    *(__half2*)(C + (long)gm0 * p.ldc + gn)       = h0;
                    *(__half2*)(C + (long)(gm0 + 8) * p.ldc + gn) = h1;
                }
            }
        }
    } else {
        float* C = (float*)Cb + cOff;
#pragma unroll
        for (int mi = 0; mi < 4; mi++) {
            int gm0 = bm + wm * 64 + mi * 16 + r;
#pragma unroll
            for (int ni = 0; ni < 8; ni++) {
                int gn = bn + wn * 64 + ni * 8 + c2;
                if (gn < p.N) {
                    float* cp0 = C + (long)gm0 * p.ldc + gn;
                    float* cp1 = C + (long)(gm0 + 8) * p.ldc + gn;
                    cp0[0] = acc[mi][ni][0]; cp0[1] = acc[mi][ni][1];
                    cp1[0] = acc[mi][ni][2]; cp1[1] = acc[mi][ni][3];
                }
            }
        }
    }
#undef FETCH
}

// ---------------- fp32 -> fp16 elementwise ----------------
__global__ void f2h(const float* __restrict__ s, __half* __restrict__ d, long n) {
    long i = ((long)blockIdx.x * blockDim.x + threadIdx.x) * 4;
    if (i < n) {
        float4 v = *(const float4*)(s + i);
        __half2 h0 = __floats2half2_rn(v.x, v.y);
        __half2 h1 = __floats2half2_rn(v.z, v.w);
        *(__half2*)(d + i)     = h0;
        *(__half2*)(d + i + 2) = h1;
    }
}

// ---------------- transpose + convert: out[c][r] = in[r][c] --------------
__global__ void transpose_h(const float* __restrict__ in, long si, long bi,
                            __half* __restrict__ out, long so, long bo) {
    __shared__ float t[32][33];
    int c0 = blockIdx.x * 32, r0 = blockIdx.y * 32;
    in  += (long)blockIdx.z * bi;
    out += (long)blockIdx.z * bo;
    int x = threadIdx.x, y = threadIdx.y;   // 32 x 8
#pragma unroll
    for (int j = 0; j < 32; j += 8)
        t[y + j][x] = in[(long)(r0 + y + j) * si + c0 + x];
    __syncthreads();
#pragma unroll
    for (int j = 0; j < 32; j += 8)
        out[(long)(c0 + y + j) * so + r0 + x] = __float2half_rn(t[x][y + j]);
}

// ---------------- RoPE ----------------
__global__ void rope_k_kernel(const float* __restrict__ ckr,
                              const float* __restrict__ fc,
                              const float* __restrict__ fs,
                              float* __restrict__ kcat) {
    int idx = blockIdx.x * blockDim.x + threadIdx.x;
    if (idx >= 2048 * 32) return;
    int m = idx >> 5, i = idx & 31;
    int t = m & 1023;
    float re = ckr[m * 64 + 2 * i], im = ckr[m * 64 + 2 * i + 1];
    float c = fc[t * 32 + i], s = fs[t * 32 + i];
    long o = (long)m * KCAT + 512 + 2 * i;
    kcat[o]     = re * c - im * s;
    kcat[o + 1] = re * s + im * c;
}

__global__ void rope_q_kernel(const float* __restrict__ cqr,
                              const float* __restrict__ fc,
                              const float* __restrict__ fs,
                              __half* __restrict__ qcat) {
    int idx = blockIdx.x * blockDim.x + threadIdx.x;
    if (idx >= 2048 * 16 * 32) return;
    int i = idx & 31;
    int h = (idx >> 5) & 15;
    int m = idx >> 9;
    int t = m & 1023, b = m >> 10;
    float re = cqr[m * 1024 + h * 64 + 2 * i];
    float im = cqr[m * 1024 + h * 64 + 2 * i + 1];
    float c = fc[t * 32 + i], s = fs[t * 32 + i];
    long o = ((long)((b * 16 + h) * 1024 + t)) * KCAT + 512 + 2 * i;
    *(__half2*)(qcat + o) = __floats2half2_rn(re * c - im * s, re * s + im * c);
}

// ---------------- causal softmax: fp32 in, fp16 out ----------------
__global__ void softmax_causal(const float* __restrict__ attn,
                               __half* __restrict__ attnh) {
    int t = blockIdx.x;
    int z = blockIdx.y;
    const float* p = attn + (long)z * 1024 * 1024 + (long)t * 1024;
    __half* ph = attnh + (long)z * 1024 * 1024 + (long)t * 1024;
    int n = t + 1;
    int lim = ((t >> 7) + 1) << 7;
    const float scale = 0.07216878364870322992f * 1.44269504088896341f;
    __shared__ float red[8];
    int tid = threadIdx.x;
    int lane = tid & 31, w = tid >> 5;

    float vals[4];
    float m = -3.4e38f;
#pragma unroll
    for (int j = 0; j < 4; j++) {
        int s = tid + j * 256;
        vals[j] = (s < n) ? p[s] * scale : -3.4e38f;
        m = fmaxf(m, vals[j]);
    }
#pragma unroll
    for (int o = 16; o > 0; o >>= 1)
        m = fmaxf(m, __shfl_xor_sync(0xffffffffu, m, o));
    if (lane == 0) red[w] = m;
    __syncthreads();
    {
        float mm = red[lane & 7];
#pragma unroll
        for (int o = 4; o > 0; o >>= 1)
            mm = fmaxf(mm, __shfl_xor_sync(0xffffffffu, mm, o));
        m = mm;
    }
    __syncthreads();

    float sum = 0.f;
#pragma unroll
    for (int j = 0; j < 4; j++) {
        int s = tid + j * 256;
        vals[j] = (s < n) ? exp2f(vals[j] - m) : 0.f;
        sum += vals[j];
    }
#pragma unroll
    for (int o = 16; o > 0; o >>= 1)
        sum += __shfl_xor_sync(0xffffffffu, sum, o);
    if (lane == 0) red[w] = sum;
    __syncthreads();
    {
        float ss = red[lane & 7];
#pragma unroll
        for (int o = 4; o > 0; o >>= 1)
            ss += __shfl_xor_sync(0xffffffffu, ss, o);
        sum = ss;
    }
    float inv = 1.f / sum;

#pragma unroll
    for (int j = 0; j < 4; j++) {
        int s = tid + j * 256;
        if (s < lim) ph[s] = __float2half_rn(vals[j] * inv);
    }
}

// ---------------- launch helpers ----------------
static void launch_gemm(const __half* A, const __half* B, void* C,
                        int M, int N, int K,
                        long sA, long sB, long ldc,
                        int batches,
                        int aDiv, long aS1, int aMod, long aS2,
                        int bDiv, long bS1, int bMod, long bS2,
                        int cDiv, long cS1, int cMod, long cS2,
                        int kSplit = 1, int mode = 0, int halfC = 0) {
    GP p;
    p.A = A; p.B = B; p.C = C;
    p.M = M; p.N = N; p.K = K;
    p.sA = sA; p.sB = sB; p.ldc = ldc;
    p.aDiv = aDiv; p.aMod = aMod; p.bDiv = bDiv; p.bMod = bMod;
    p.cDiv = cDiv; p.cMod = cMod;
    p.aS1 = aS1; p.aS2 = aS2; p.bS1 = bS1; p.bS2 = bS2; p.cS1 = cS1; p.cS2 = cS2;
    p.kSplit = kSplit; p.mode = mode; p.halfC = halfC;
    dim3 grid((N + 127) / 128, (M + 127) / 128, batches * kSplit);
    hgemm<<<grid, 128>>>(p);
}

static void launch_f2h(const float* s, __half* d, long n) {
    f2h<<<(unsigned)((n / 4 + 255) / 256), 256>>>(s, d, n);
}

extern "C" void kernel_launch(void* const* d_in, const int* in_sizes, int n_in,
                              void* d_out, int out_size) {
    const float* x     = (const float*)d_in[0];
    const float* fcos  = (const float*)d_in[1];
    const float* fsin  = (const float*)d_in[2];
    const float* W_dq  = (const float*)d_in[3];
    const float* W_uq  = (const float*)d_in[4];
    const float* W_dkv = (const float*)d_in[5];
    const float* W_uk  = (const float*)d_in[6];
    const float* W_uv  = (const float*)d_in[7];
    const float* W_qr  = (const float*)d_in[8];
    const float* W_kr  = (const float*)d_in[9];
    const float* W_o   = (const float*)d_in[10];
    float* out = (float*)d_out;

    float *cq, *ckr, *cqr, *kcat, *veff, *attn;
    cudaGetSymbolAddress((void**)&cq,   g_cq);
    cudaGetSymbolAddress((void**)&ckr,  g_ckr);
    cudaGetSymbolAddress((void**)&cqr,  g_cqr);
    cudaGetSymbolAddress((void**)&kcat, g_kcat);
    cudaGetSymbolAddress((void**)&veff, g_veff);
    cudaGetSymbolAddress((void**)&attn, g_attn);

    __half *xh, *wdqh, *wdkvh, *wkrh, *wqrh, *woh, *wuqh, *wukT, *wuvT;
    __half *keffh, *veffh, *cqh, *kcath, *ckvth, *qcath, *attnh, *lath;
    cudaGetSymbolAddress((void**)&xh,    h_x);
    cudaGetSymbolAddress((void**)&wdqh,  h_wdq);
    cudaGetSymbolAddress((void**)&wdkvh, h_wdkv);
    cudaGetSymbolAddress((void**)&wkrh,  h_wkr);
    cudaGetSymbolAddress((void**)&wqrh,  h_wqr);
    cudaGetSymbolAddress((void**)&woh,   h_wo);
    cudaGetSymbolAddress((void**)&wuqh,  h_wuq);
    cudaGetSymbolAddress((void**)&wukT,  h_wukT);
    cudaGetSymbolAddress((void**)&wuvT,  h_wuvT);
    cudaGetSymbolAddress((void**)&keffh, h_keff);
    cudaGetSymbolAddress((void**)&veffh, h_veff);
    cudaGetSymbolAddress((void**)&cqh,   h_cq);
    cudaGetSymbolAddress((void**)&kcath, h_kcat);
    cudaGetSymbolAddress((void**)&ckvth, h_ckvt);
    cudaGetSymbolAddress((void**)&qcath, h_qcat);
    cudaGetSymbolAddress((void**)&attnh, h_attn);
    cudaGetSymbolAddress((void**)&lath,  h_lat);

    cudaMemsetAsync(veff, 0, 2048l * 512 * 4);
    cudaMemsetAsync(cq,   0, 2048l * 512 * 4);
    cudaMemsetAsync(ckr,  0, 2048l * 64 * 4);
    cudaMemsetAsync(cqr,  0, 2048l * 1024 * 4);
    cudaMemsetAsync(kcat, 0, 2048l * 576 * 4);

    // 0) convert inputs to fp16 (+ transposes for K-contiguity)
    launch_f2h(x,     xh,    4194304);
    launch_f2h(W_dq,  wdqh,  1048576);
    launch_f2h(W_dkv, wdkvh, 1048576);
    launch_f2h(W_kr,  wkrh,  131072);
    launch_f2h(W_qr,  wqrh,  524288);
    launch_f2h(W_o,   woh,   4194304);
    launch_f2h(W_uq,  wuqh,  1048576);
    {   // wukT[h][k][d] = W_uk[(h*128+d)*512 + k]
        dim3 g(512 / 32, 128 / 32, 16), b(32, 8);
        transpose_h<<<g, b>>>(W_uk, 512, 128l * 512, wukT, 128, 512l * 128);
    }
    {   // wuvT[k'][c] = W_uv[c*512 + k']
        dim3 g(512 / 32, 2048 / 32, 1), b(32, 8);
        transpose_h<<<g, b>>>(W_uv, 512, 0, wuvT, 2048, 0);
    }

    // 1) keff_t[h][k][q] = sum_d wukT[h][k][d] * wuqh[q][h*128+d]  (halfC)
    launch_gemm(wukT, wuqh, keffh, 512, 512, 128,
                128, 2048, 512, 16,
                1, 0, 16, 512l * 128,
                1, 0, 16, 128,
                1, 0, 16, 512l * 512, 1, 0, 1);

    // 2) veff_t[j][k'] = sum_c woh[j][c] * wuvT[k'][c]  (split-K 8)
    launch_gemm(woh, wuvT, veff, 2048, 512, 2048,
                2048, 2048, 512, 1,
                1, 0, 1, 0, 1, 0, 1, 0, 1, 0, 1, 0, 8);
    launch_f2h(veff, veffh, 1048576);

    // 3) c_q = x @ W_dq^T  (split-K 8)
    launch_gemm(xh, wdqh, cq, 2048, 512, 2048,
                2048, 2048, 512, 1,
                1, 0, 1, 0, 1, 0, 1, 0, 1, 0, 1, 0, 8);
    launch_f2h(cq, cqh, 1048576);

    // 4) c_kv -> kcat cols [0,512)  (split-K 8)
    launch_gemm(xh, wdkvh, kcat, 2048, 512, 2048,
                2048, 2048, KCAT, 1,
                1, 0, 1, 0, 1, 0, 1, 0, 1, 0, 1, 0, 8);

    // 5) c_kr  (split-K 16)
    launch_gemm(xh, wkrh, ckr, 2048, 64, 2048,
                2048, 2048, 64, 1,
                1, 0, 1, 0, 1, 0, 1, 0, 1, 0, 1, 0, 16);

    // 6) c_qr = c_q @ W_qr^T  (split-K 4)
    launch_gemm(cqh, wqrh, cqr, 2048, 1024, 512,
                512, 512, 1024, 1,
                1, 0, 1, 0, 1, 0, 1, 0, 1, 0, 1, 0, 4);

    // 7) RoPE k (fp32), then convert kcat -> kcath and transpose c_kv -> ckvth
    rope_k_kernel<<<(2048 * 32 + 255) / 256, 256>>>(ckr, fcos, fsin, kcat);
    launch_f2h(kcat, kcath, 2048l * 576);
    {   // ckvth[b][k'][s] = kcat[b*1024+s][k']  (cols 0..512 only)
        dim3 g(512 / 32, 1024 / 32, 2), b(32, 8);
        transpose_h<<<g, b>>>(kcat, 576, 1024l * 576, ckvth, 1024, 512l * 1024);
    }

    // 8) RoPE q -> qcath cols [512,576)
    rope_q_kernel<<<(2048 * 16 * 32 + 255) / 256, 256>>>(cqr, fcos, fsin, qcath);

    // 9) q_abs = cq @ keff_t^T -> qcath cols [0,512)  (halfC)
    launch_gemm(cqh, keffh, qcath, 1024, 512, 512,
                512, 512, KCAT, 32,
                16, 1024l * 512, 1, 0,
                1, 0, 16, 512l * 512,
                1, 0, 32, 1024l * KCAT, 1, 0, 1);

    // 10) logits = qcat @ kcat^T  (causal tile-skip; fp32 out)
    launch_gemm(qcath, kcath, attn, 1024, 1024, KCAT,
                KCAT, KCAT, 1024, 32,
                1, 0, 32, 1024l * KCAT,
                16, 1024l * KCAT, 1, 0,
                1, 0, 32, 1024l * 1024, 1, 1);

    // 11) softmax: fp32 attn -> fp16 attnh
    {
        dim3 grid(1024, 32);
        softmax_causal<<<grid, 256>>>(attn, attnh);
    }

    // 12) lat = attn @ c_kv  (causal k-stop; halfC)
    launch_gemm(attnh, ckvth, lath, 1024, 512, 1024,
                1024, 1024, 512, 32,
                1, 0, 32, 1024l * 1024,
                16, 512l * 1024, 1, 0,
                1, 0, 32, 1024l * 512, 1, 2, 1);

    // 13) y = lat @ veff_t^T  (fp32 out)
    launch_gemm(lath, veffh, out, 1024, 128, 512,
                512, 512, 2048, 32,
                1, 0, 32, 1024l * 512,
                1, 0, 16, 128l * 512,
                16, 1024l * 2048, 16, 128);
}